// round 5
// baseline (speedup 1.0000x reference)
#include <cuda_runtime.h>
#include <cuda_bf16.h>
#include <cstdint>

#define B_ 4
#define N_ 16384
#define M_ 16384
#define K_ 16
#define C_ 64
#define O_ 64
#define G_ 8

// ---------------- device scratch (no allocations allowed) -------------------
__device__ __align__(16) float g_xv[(size_t)B_ * N_ * O_];   // x_v per point
__device__ __align__(16) float g_kgp[(size_t)B_ * N_ * G_];  // x_k @ we_w1' (+bias)
__device__ __align__(16) float g_qw[(size_t)B_ * M_ * G_];   // (cpr - x_q)@we_w1' + we_b

// ============================================================================
// k12: fused point-side (z=0) and center-side (z=1) projections, with the
// we_w1*we_s fold recomputed per block from shared-staged weights.
// grid (256, B, 2), block 256.
// ============================================================================
__global__ void __launch_bounds__(256) k12(
    const float* __restrict__ fea, const float* __restrict__ Wv, const float* __restrict__ bv,
    const float* __restrict__ Wk, const float* __restrict__ bk,
    const float* __restrict__ cfea, const float* __restrict__ cpos,
    const float* __restrict__ cpe_w1, const float* __restrict__ cpe_s, const float* __restrict__ cpe_b,
    const float* __restrict__ cpe_w2, const float* __restrict__ cpe_b2,
    const float* __restrict__ Wq, const float* __restrict__ bq,
    const float* __restrict__ we_w1, const float* __restrict__ we_s, const float* __restrict__ we_b)
{
    __shared__ __align__(16) float smem[9224];
    float* w1p = smem;                     // [64][8] folded we_w1*we_s
    int t = threadIdx.x;
    int b = blockIdx.y;

    for (int i = t; i < 512; i += 256) w1p[i] = we_w1[i] * we_s[i & 7];

    if (blockIdx.z == 0) {
        // ---------------- k1: x_v and kgp per point ----------------
        float* sWkP = smem + 512;          // [64][8]
        float* sbkP = smem + 1024;         // [8]
        float* sfea = smem + 1032;         // [64][64]
        float* sWv  = smem + 5128;         // [64][64]

        // stage Wk into sWv buffer for the fold
        for (int i = t; i < 4096; i += 256) sWv[i] = Wk[i];
        __syncthreads();
        for (int i = t; i < 512; i += 256) {
            int c = i >> 3, g = i & 7;
            float a = 0.f;
            #pragma unroll 8
            for (int o = 0; o < 64; o++) a = fmaf(sWv[c * 64 + o], w1p[o * 8 + g], a);
            sWkP[i] = a;
        }
        if (t < 8) {
            float a = 0.f;
            for (int o = 0; o < 64; o++) a = fmaf(bk[o], w1p[o * 8 + t], a);
            sbkP[t] = a;
        }
        __syncthreads();

        int n0 = blockIdx.x * 64;
        const float* fbase = fea + (size_t)b * C_ * N_ + n0;
        for (int i = t; i < 4096; i += 256) {
            int c = i >> 6, n = i & 63;
            sfea[c * 64 + n] = fbase[(size_t)c * N_ + n];
        }
        for (int i = t; i < 4096; i += 256) sWv[i] = Wv[i];
        __syncthreads();

        int n = t & 63, q = t >> 6;
        int ob = q * 16;
        int g0 = 2 * q;
        float acc[16];
        #pragma unroll
        for (int u = 0; u < 16; u++) acc[u] = bv[ob + u];
        float ak0 = sbkP[g0], ak1 = sbkP[g0 + 1];

        #pragma unroll 4
        for (int c = 0; c < 64; c++) {
            float f = sfea[c * 64 + n];
            #pragma unroll
            for (int u = 0; u < 16; u++) acc[u] = fmaf(f, sWv[c * 64 + ob + u], acc[u]);
            ak0 = fmaf(f, sWkP[c * 8 + g0],     ak0);
            ak1 = fmaf(f, sWkP[c * 8 + g0 + 1], ak1);
        }

        float* xvo = &g_xv[((size_t)b * N_ + n0 + n) * O_ + ob];
        #pragma unroll
        for (int u = 0; u < 16; u += 4)
            *(float4*)(xvo + u) = make_float4(acc[u], acc[u + 1], acc[u + 2], acc[u + 3]);
        *(float2*)&g_kgp[((size_t)b * N_ + n0 + n) * G_ + g0] = make_float2(ak0, ak1);
    } else {
        // ---------------- k2: qw per center ----------------
        float* sWqP  = smem + 512;         // [64][8]
        float* scw2P = smem + 1024;        // [64][8]
        float* sqc   = smem + 1536;        // [8]
        float* sfea  = smem + 1544;        // [64][64]
        float* sw1   = smem + 5640;        // [3][64]
        float* ss    = smem + 5832;        // [64]
        float* sb    = smem + 5896;        // [64]

        // fold Wq (staged in sfea)
        for (int i = t; i < 4096; i += 256) sfea[i] = Wq[i];
        __syncthreads();
        for (int i = t; i < 512; i += 256) {
            int c = i >> 3, g = i & 7;
            float a = 0.f;
            #pragma unroll 8
            for (int o = 0; o < 64; o++) a = fmaf(sfea[c * 64 + o], w1p[o * 8 + g], a);
            sWqP[i] = a;
        }
        __syncthreads();
        // fold cpe_w2 (staged in sfea)
        for (int i = t; i < 4096; i += 256) sfea[i] = cpe_w2[i];
        __syncthreads();
        for (int i = t; i < 512; i += 256) {
            int c = i >> 3, g = i & 7;
            float a = 0.f;
            #pragma unroll 8
            for (int o = 0; o < 64; o++) a = fmaf(sfea[c * 64 + o], w1p[o * 8 + g], a);
            scw2P[i] = a;
        }
        if (t < 8) {
            float a = we_b[t];
            for (int o = 0; o < 64; o++) a = fmaf(cpe_b2[o] - bq[o], w1p[o * 8 + t], a);
            sqc[t] = a;
        }
        __syncthreads();

        int m0 = blockIdx.x * 64;
        const float* fbase = cfea + (size_t)b * C_ * M_ + m0;
        for (int i = t; i < 4096; i += 256) {
            int c = i >> 6, m = i & 63;
            sfea[c * 64 + m] = fbase[(size_t)c * M_ + m];
        }
        for (int i = t; i < 192; i += 256) sw1[i] = cpe_w1[i];
        if (t < 64) { ss[t] = cpe_s[t]; sb[t] = cpe_b[t]; }
        __syncthreads();

        int m = t & 63, q = t >> 6, g0 = 2 * q;
        float a0 = sqc[g0], a1 = sqc[g0 + 1];

        #pragma unroll 4
        for (int c = 0; c < 64; c++) {
            float f = sfea[c * 64 + m];
            a0 = fmaf(-f, sWqP[c * 8 + g0],     a0);
            a1 = fmaf(-f, sWqP[c * 8 + g0 + 1], a1);
        }
        const float* cp = cpos + ((size_t)b * M_ + m0 + m) * 3;
        float x = cp[0], y = cp[1], z = cp[2];
        #pragma unroll 4
        for (int o = 0; o < 64; o++) {
            float d  = fmaf(z, sw1[128 + o], fmaf(y, sw1[64 + o], x * sw1[o]));
            float rc = fmaxf(fmaf(d, ss[o], sb[o]), 0.f);
            a0 = fmaf(rc, scw2P[o * 8 + g0],     a0);
            a1 = fmaf(rc, scw2P[o * 8 + g0 + 1], a1);
        }
        *(float2*)&g_qw[((size_t)b * M_ + m0 + m) * G_ + g0] = make_float2(a0, a1);
    }
}

// ============================================================================
// k3: main attention. 2 centers/warp, 16 centers/block. Softmax weights for
// Phase B come from Phase A registers via warp shuffle (off the L1 pipe).
// ============================================================================
__global__ void __launch_bounds__(256, 3) k3_main(
    const float* __restrict__ cpos, const float* __restrict__ pos,
    const int*   __restrict__ idx,
    const float* __restrict__ pe_w1, const float* __restrict__ pe_s, const float* __restrict__ pe_b,
    const float* __restrict__ pe_w2, const float* __restrict__ pe_b2,
    const float* __restrict__ we_w2, const float* __restrict__ we_b2,
    float* __restrict__ out)
{
    extern __shared__ __align__(16) char dyns[];
    float*  s_pew2 = (float*)dyns;                 // [64][68]
    float*  s_stg  = s_pew2 + 64 * 68;             // [8][2][8][36]
    float*  s_w    = s_stg  + 4608;                // [16][16][8]
    float4* s_npos = (float4*)(s_w + 2048);        // [16][16]
    float*  s_out  = (float*)(s_npos + 256);       // [16][68]
    int*    s_nidx = (int*)(s_out + 1088);         // [16][16]
    float*  s_pes  = (float*)(s_nidx + 256);       // 64
    float*  s_peb  = s_pes + 64;                   // 64
    float*  s_peb2 = s_peb + 64;                   // 64
    float*  s_wew2 = s_peb2 + 64;                  // 64
    float*  s_web2 = s_wew2 + 64;                  // 8

    int b = blockIdx.y;
    int m_base = blockIdx.x * 16;
    int t = threadIdx.x;
    int w = t >> 5, l = t & 31;

    // ---- cooperative constant loads ----
    for (int i = t; i < 64 * 64; i += 256) { int j = i >> 6, o = i & 63; s_pew2[j * 68 + o] = pe_w2[i]; }
    for (int i = t; i < 64; i += 256) { s_pes[i] = pe_s[i]; s_peb[i] = pe_b[i]; s_peb2[i] = pe_b2[i]; }
    if (t < 64) s_wew2[t] = we_w2[t];
    if (t < 8)  s_web2[t] = we_b2[t];

    int half = l >> 4;            // 0/1: which center of the warp's pair
    int cc   = w * 2 + half;
    int m    = m_base + cc;

    // ---- neighbor setup: lane (half, k=l&15) ----
    {
        int k = l & 15;
        int n = idx[((size_t)b * M_ + m) * K_ + k];
        s_nidx[cc * 16 + k] = n;
        const float* pp = pos  + ((size_t)b * N_ + n) * 3;
        const float* cp = cpos + ((size_t)b * M_ + m) * 3;
        s_npos[cc * 16 + k] = make_float4(pp[0] - cp[0], pp[1] - cp[1], pp[2] - cp[2], 0.f);
    }
    __syncthreads();

    // ---- Phase A: logits + softmax; weights stay in wreg[8] ----
    float wreg[8];
    {
        int k = l & 15;
        int n = s_nidx[cc * 16 + k];
        const float4* qwp = (const float4*)&g_qw[((size_t)b * M_ + m) * G_];
        float4 qa = qwp[0], qb = qwp[1];
        const float4* kgp = (const float4*)&g_kgp[((size_t)b * N_ + n) * G_];
        float4 k0 = kgp[0], k1 = kgp[1];
        float h[8];
        h[0] = fmaxf(k0.x + qa.x, 0.f); h[1] = fmaxf(k0.y + qa.y, 0.f);
        h[2] = fmaxf(k0.z + qa.z, 0.f); h[3] = fmaxf(k0.w + qa.w, 0.f);
        h[4] = fmaxf(k1.x + qb.x, 0.f); h[5] = fmaxf(k1.y + qb.y, 0.f);
        h[6] = fmaxf(k1.z + qb.z, 0.f); h[7] = fmaxf(k1.w + qb.w, 0.f);

        float4 lgA = *(const float4*)&s_web2[0];
        float4 lgB = *(const float4*)&s_web2[4];
        #pragma unroll
        for (int j = 0; j < 8; j++) {
            float hj = h[j];
            float4 wA = *(const float4*)&s_wew2[j * 8];
            float4 wB = *(const float4*)&s_wew2[j * 8 + 4];
            lgA.x = fmaf(hj, wA.x, lgA.x); lgA.y = fmaf(hj, wA.y, lgA.y);
            lgA.z = fmaf(hj, wA.z, lgA.z); lgA.w = fmaf(hj, wA.w, lgA.w);
            lgB.x = fmaf(hj, wB.x, lgB.x); lgB.y = fmaf(hj, wB.y, lgB.y);
            lgB.z = fmaf(hj, wB.z, lgB.z); lgB.w = fmaf(hj, wB.w, lgB.w);
        }
        float lg[8] = {lgA.x, lgA.y, lgA.z, lgA.w, lgB.x, lgB.y, lgB.z, lgB.w};
        float mx[8];
        #pragma unroll
        for (int u = 0; u < 8; u++) mx[u] = lg[u];
        #pragma unroll
        for (int mask = 1; mask <= 8; mask <<= 1)
            #pragma unroll
            for (int u = 0; u < 8; u++)
                mx[u] = fmaxf(mx[u], __shfl_xor_sync(0xffffffffu, mx[u], mask));
        float e[8], sm[8];
        #pragma unroll
        for (int u = 0; u < 8; u++) { e[u] = __expf(lg[u] - mx[u]); sm[u] = e[u]; }
        #pragma unroll
        for (int mask = 1; mask <= 8; mask <<= 1)
            #pragma unroll
            for (int u = 0; u < 8; u++)
                sm[u] += __shfl_xor_sync(0xffffffffu, sm[u], mask);
        #pragma unroll
        for (int u = 0; u < 8; u++) wreg[u] = e[u] / sm[u];
        float* wp = &s_w[(cc * 16 + (l & 15)) * 8];
        *(float4*)&wp[0] = make_float4(wreg[0], wreg[1], wreg[2], wreg[3]);
        *(float4*)&wp[4] = make_float4(wreg[4], wreg[5], wreg[6], wreg[7]);
    }
    __syncwarp();

    // ---- Phase B: S[c][g][j] in registers; weights via shuffle ----
    float S0[2][8], S1[2][8];
    {
        int j0 = 2 * l, j1 = j0 + 1;
        float wx0 = pe_w1[j0], wy0 = pe_w1[64 + j0], wz0 = pe_w1[128 + j0];
        float wx1 = pe_w1[j1], wy1 = pe_w1[64 + j1], wz1 = pe_w1[128 + j1];
        float ps0 = s_pes[j0], pb0 = s_peb[j0];
        float ps1 = s_pes[j1], pb1 = s_peb[j1];

        #pragma unroll
        for (int c = 0; c < 2; c++) {
            int ccB = w * 2 + c;
            #pragma unroll
            for (int g = 0; g < 8; g++) { S0[c][g] = 0.f; S1[c][g] = 0.f; }
            #pragma unroll
            for (int kk = 0; kk < 16; kk++) {
                float4 np = s_npos[ccB * 16 + kk];
                float d0 = fmaf(np.z, wz0, fmaf(np.y, wy0, np.x * wx0));
                float d1 = fmaf(np.z, wz1, fmaf(np.y, wy1, np.x * wx1));
                float t0 = fmaxf(fmaf(d0, ps0, pb0), 0.f);
                float t1 = fmaxf(fmaf(d1, ps1, pb1), 0.f);
                int src = c * 16 + kk;
                #pragma unroll
                for (int g = 0; g < 8; g++) {
                    float wv = __shfl_sync(0xffffffffu, wreg[g], src);
                    S0[c][g] = fmaf(t0, wv, S0[c][g]);
                    S1[c][g] = fmaf(t1, wv, S1[c][g]);
                }
            }
        }
    }

    // ---- Phase C: chunked over j (2 chunks of 32). lane: (half, o0=(l&15)*4) ----
    {
        int lo = l & 15;
        int o0 = lo * 4;
        int g  = lo >> 1;                      // = o0 >> 3
        float4 acc = *(const float4*)&s_peb2[o0];
        float* stg = &s_stg[((w * 2 + half) * 8 + g) * 36];
        int myChunk = l >> 4;                  // which chunk this lane's S regs belong to
        int jl = (l & 15) * 2;                 // local j within chunk

        #pragma unroll
        for (int ch = 0; ch < 2; ch++) {
            if (myChunk == ch) {
                #pragma unroll
                for (int c = 0; c < 2; c++) {
                    float* dst = &s_stg[((w * 2 + c) * 8) * 36];
                    #pragma unroll
                    for (int gg = 0; gg < 8; gg++)
                        *(float2*)&dst[gg * 36 + jl] = make_float2(S0[c][gg], S1[c][gg]);
                }
            }
            __syncwarp();
            int jb = ch * 32;
            #pragma unroll
            for (int jq = 0; jq < 32; jq += 4) {
                float4 sv  = *(const float4*)&stg[jq];
                const float* wrow = &s_pew2[(jb + jq) * 68 + o0];
                float4 w20 = *(const float4*)(wrow);
                float4 w21 = *(const float4*)(wrow + 68);
                float4 w22 = *(const float4*)(wrow + 136);
                float4 w23 = *(const float4*)(wrow + 204);
                acc.x = fmaf(sv.x, w20.x, acc.x); acc.y = fmaf(sv.x, w20.y, acc.y);
                acc.z = fmaf(sv.x, w20.z, acc.z); acc.w = fmaf(sv.x, w20.w, acc.w);
                acc.x = fmaf(sv.y, w21.x, acc.x); acc.y = fmaf(sv.y, w21.y, acc.y);
                acc.z = fmaf(sv.y, w21.z, acc.z); acc.w = fmaf(sv.y, w21.w, acc.w);
                acc.x = fmaf(sv.z, w22.x, acc.x); acc.y = fmaf(sv.z, w22.y, acc.y);
                acc.z = fmaf(sv.z, w22.z, acc.z); acc.w = fmaf(sv.z, w22.w, acc.w);
                acc.x = fmaf(sv.w, w23.x, acc.x); acc.y = fmaf(sv.w, w23.y, acc.y);
                acc.z = fmaf(sv.w, w23.z, acc.z); acc.w = fmaf(sv.w, w23.w, acc.w);
            }
            __syncwarp();
        }

        // xv gather part
        const float* xvb = &g_xv[((size_t)b * N_) * O_];
        #pragma unroll
        for (int kk = 0; kk < 16; kk++) {
            int   n  = s_nidx[cc * 16 + kk];
            float wk = s_w[(cc * 16 + kk) * 8 + g];
            float4 xv = *(const float4*)&xvb[(size_t)n * O_ + o0];
            acc.x = fmaf(wk, xv.x, acc.x);
            acc.y = fmaf(wk, xv.y, acc.y);
            acc.z = fmaf(wk, xv.z, acc.z);
            acc.w = fmaf(wk, xv.w, acc.w);
        }
        *(float4*)&s_out[cc * 68 + o0] = acc;
    }
    __syncthreads();

    // ---- coalesced transposed store: out[b][o][m_base + 0..15] ----
    {
        int mm = t & 15;
        #pragma unroll
        for (int o = t >> 4; o < 64; o += 16)
            out[((size_t)b * O_ + o) * M_ + m_base + mm] = s_out[mm * 68 + o];
    }
}

// ============================================================================
extern "C" void kernel_launch(void* const* d_in, const int* in_sizes, int n_in,
                              void* d_out, int out_size)
{
    const float* center_pos = (const float*)d_in[0];
    const float* center_fea = (const float*)d_in[1];
    const float* pos        = (const float*)d_in[2];
    const float* fea        = (const float*)d_in[3];
    const int*   idx        = (const int*)  d_in[4];
    const float* Wq   = (const float*)d_in[5];
    const float* bq   = (const float*)d_in[6];
    const float* Wk   = (const float*)d_in[7];
    const float* bk   = (const float*)d_in[8];
    const float* Wv   = (const float*)d_in[9];
    const float* bv   = (const float*)d_in[10];
    const float* cpe_w1 = (const float*)d_in[11];
    const float* cpe_s  = (const float*)d_in[12];
    const float* cpe_b  = (const float*)d_in[13];
    const float* cpe_w2 = (const float*)d_in[14];
    const float* cpe_b2 = (const float*)d_in[15];
    const float* pe_w1  = (const float*)d_in[16];
    const float* pe_s   = (const float*)d_in[17];
    const float* pe_b   = (const float*)d_in[18];
    const float* pe_w2  = (const float*)d_in[19];
    const float* pe_b2  = (const float*)d_in[20];
    const float* we_w1  = (const float*)d_in[21];
    const float* we_s   = (const float*)d_in[22];
    const float* we_b   = (const float*)d_in[23];
    const float* we_w2  = (const float*)d_in[24];
    const float* we_b2  = (const float*)d_in[25];
    float* out = (float*)d_out;

    const int SMEM_K3 = 54560;
    static int attr_set = 0;
    if (!attr_set) {
        cudaFuncSetAttribute(k3_main, cudaFuncAttributeMaxDynamicSharedMemorySize, SMEM_K3);
        attr_set = 1;
    }

    dim3 g12(N_ / 64, B_, 2);
    k12<<<g12, 256>>>(fea, Wv, bv, Wk, bk,
                      center_fea, center_pos, cpe_w1, cpe_s, cpe_b,
                      cpe_w2, cpe_b2, Wq, bq,
                      we_w1, we_s, we_b);

    dim3 g3(M_ / 16, B_);
    k3_main<<<g3, 256, SMEM_K3>>>(center_pos, pos, idx,
                                  pe_w1, pe_s, pe_b, pe_w2, pe_b2,
                                  we_w2, we_b2, out);
}

// round 6
// speedup vs baseline: 1.2826x; 1.2826x over previous
#include <cuda_runtime.h>
#include <cuda_bf16.h>
#include <cuda_fp16.h>
#include <cstdint>

#define B_ 4
#define N_ 16384
#define M_ 16384
#define K_ 16
#define C_ 64
#define O_ 64
#define G_ 8

// ---------------- device scratch (no allocations allowed) -------------------
__device__ __align__(16) float  g_WkP[C_ * G_];
__device__ __align__(16) float  g_bkP[G_];
__device__ __align__(16) float  g_WqP[C_ * G_];
__device__ __align__(16) float  g_cw2P[O_ * G_];
__device__ __align__(16) float  g_qconst[G_];
__device__ __align__(16) __half g_xvh[(size_t)B_ * N_ * O_];  // x_v per point (fp16)
__device__ __align__(16) float  g_kgp[(size_t)B_ * N_ * G_];  // x_k @ we_w1' (+bias)
__device__ __align__(16) float  g_qw[(size_t)B_ * M_ * G_];   // (cpr-x_q)@we_w1' + we_b

// Load 4 consecutive halfs -> float4 (8-byte aligned)
__device__ __forceinline__ float4 ld_h4(const __half* p) {
    uint2 r = *(const uint2*)p;
    __half2 h0 = *reinterpret_cast<__half2*>(&r.x);
    __half2 h1 = *reinterpret_cast<__half2*>(&r.y);
    float2 f0 = __half22float2(h0);
    float2 f1 = __half22float2(h1);
    return make_float4(f0.x, f0.y, f1.x, f1.y);
}

// ============================================================================
// k0: fold we_w1*we_s through Wk, Wq, cpe_w2; fold biases.  1 block, 64 thr.
// ============================================================================
__global__ void k0_fold(const float* __restrict__ Wq, const float* __restrict__ bq,
                        const float* __restrict__ Wk, const float* __restrict__ bk,
                        const float* __restrict__ cpe_w2, const float* __restrict__ cpe_b2,
                        const float* __restrict__ we_w1, const float* __restrict__ we_s,
                        const float* __restrict__ we_b)
{
    __shared__ float w1p[O_][G_];
    int t = threadIdx.x;  // 0..63
    #pragma unroll
    for (int g = 0; g < G_; g++) w1p[t][g] = we_w1[t * G_ + g] * we_s[g];
    __syncthreads();

    float accK[G_], accQ[G_], accC[G_];
    #pragma unroll
    for (int g = 0; g < G_; g++) { accK[g] = 0.f; accQ[g] = 0.f; accC[g] = 0.f; }
    for (int o = 0; o < O_; o++) {
        float wk = Wk[t * O_ + o];
        float wq = Wq[t * O_ + o];
        float cw = cpe_w2[t * O_ + o];
        #pragma unroll
        for (int g = 0; g < G_; g++) {
            accK[g] = fmaf(wk, w1p[o][g], accK[g]);
            accQ[g] = fmaf(wq, w1p[o][g], accQ[g]);
            accC[g] = fmaf(cw, w1p[o][g], accC[g]);
        }
    }
    #pragma unroll
    for (int g = 0; g < G_; g++) {
        g_WkP[t * G_ + g]  = accK[g];
        g_WqP[t * G_ + g]  = accQ[g];
        g_cw2P[t * G_ + g] = accC[g];
    }
    if (t < G_) {
        float bkp = 0.f, bqp = 0.f, cb2p = 0.f;
        for (int o = 0; o < O_; o++) {
            bkp  = fmaf(bk[o],      w1p[o][t], bkp);
            bqp  = fmaf(bq[o],      w1p[o][t], bqp);
            cb2p = fmaf(cpe_b2[o],  w1p[o][t], cb2p);
        }
        g_bkP[t]    = bkp;
        g_qconst[t] = cb2p - bqp + we_b[t];
    }
}

// ============================================================================
// k12: fused point-side (z=0) and center-side (z=1) projections, using k0's
// pre-folded weights (no per-block re-fold).  grid (256, B, 2), block 256.
// ============================================================================
__global__ void __launch_bounds__(256) k12(
    const float* __restrict__ fea, const float* __restrict__ Wv, const float* __restrict__ bv,
    const float* __restrict__ cfea, const float* __restrict__ cpos,
    const float* __restrict__ cpe_w1, const float* __restrict__ cpe_s, const float* __restrict__ cpe_b)
{
    __shared__ __align__(16) float smem[8784];
    int t = threadIdx.x;
    int b = blockIdx.y;

    if (blockIdx.z == 0) {
        // ---------------- x_v (fp16) and kgp per point ----------------
        float* sfea = smem;              // [64][64]
        float* sWv  = smem + 4096;       // [64][64]
        float* sWkP = smem + 8192;       // [64][8]
        float* sbkP = smem + 8704;       // [8]

        int n0 = blockIdx.x * 64;
        const float* fbase = fea + (size_t)b * C_ * N_ + n0;
        for (int i = t; i < 4096; i += 256) {
            int c = i >> 6, n = i & 63;
            sfea[c * 64 + n] = fbase[(size_t)c * N_ + n];
        }
        for (int i = t; i < 4096; i += 256) sWv[i] = Wv[i];
        for (int i = t; i < 512;  i += 256) sWkP[i] = g_WkP[i];
        if (t < 8) sbkP[t] = g_bkP[t];
        __syncthreads();

        int n = t & 63, q = t >> 6;
        int ob = q * 16;
        int g0 = 2 * q;
        float acc[16];
        #pragma unroll
        for (int u = 0; u < 16; u++) acc[u] = bv[ob + u];
        float ak0 = sbkP[g0], ak1 = sbkP[g0 + 1];

        #pragma unroll 4
        for (int c = 0; c < 64; c++) {
            float f = sfea[c * 64 + n];
            #pragma unroll
            for (int u = 0; u < 16; u++) acc[u] = fmaf(f, sWv[c * 64 + ob + u], acc[u]);
            ak0 = fmaf(f, sWkP[c * 8 + g0],     ak0);
            ak1 = fmaf(f, sWkP[c * 8 + g0 + 1], ak1);
        }

        __half* xvo = &g_xvh[((size_t)b * N_ + n0 + n) * O_ + ob];
        union { uint4 u; __half2 h[4]; } p0, p1;
        #pragma unroll
        for (int u = 0; u < 4; u++) p0.h[u] = __floats2half2_rn(acc[2 * u],     acc[2 * u + 1]);
        #pragma unroll
        for (int u = 0; u < 4; u++) p1.h[u] = __floats2half2_rn(acc[8 + 2 * u], acc[8 + 2 * u + 1]);
        *(uint4*)xvo       = p0.u;
        *(uint4*)(xvo + 8) = p1.u;
        *(float2*)&g_kgp[((size_t)b * N_ + n0 + n) * G_ + g0] = make_float2(ak0, ak1);
    } else {
        // ---------------- qw per center ----------------
        float* sfea  = smem;             // [64][64]
        float* sWqP  = smem + 4096;      // [64][8]
        float* scw2P = smem + 4608;      // [64][8]
        float* sw1   = smem + 5120;      // [3][64]
        float* ss    = smem + 5312;      // [64]
        float* sb    = smem + 5376;      // [64]
        float* sqc   = smem + 5440;      // [8]

        int m0 = blockIdx.x * 64;
        const float* fbase = cfea + (size_t)b * C_ * M_ + m0;
        for (int i = t; i < 4096; i += 256) {
            int c = i >> 6, m = i & 63;
            sfea[c * 64 + m] = fbase[(size_t)c * M_ + m];
        }
        for (int i = t; i < 512; i += 256) { sWqP[i] = g_WqP[i]; scw2P[i] = g_cw2P[i]; }
        if (t < 192) sw1[t] = cpe_w1[t];
        if (t < 64)  { ss[t] = cpe_s[t]; sb[t] = cpe_b[t]; }
        if (t < 8)   sqc[t] = g_qconst[t];
        __syncthreads();

        int m = t & 63, q = t >> 6, g0 = 2 * q;
        float a0 = sqc[g0], a1 = sqc[g0 + 1];

        #pragma unroll 4
        for (int c = 0; c < 64; c++) {
            float f = sfea[c * 64 + m];
            a0 = fmaf(-f, sWqP[c * 8 + g0],     a0);
            a1 = fmaf(-f, sWqP[c * 8 + g0 + 1], a1);
        }
        const float* cp = cpos + ((size_t)b * M_ + m0 + m) * 3;
        float x = cp[0], y = cp[1], z = cp[2];
        #pragma unroll 4
        for (int o = 0; o < 64; o++) {
            float d  = fmaf(z, sw1[128 + o], fmaf(y, sw1[64 + o], x * sw1[o]));
            float rc = fmaxf(fmaf(d, ss[o], sb[o]), 0.f);
            a0 = fmaf(rc, scw2P[o * 8 + g0],     a0);
            a1 = fmaf(rc, scw2P[o * 8 + g0 + 1], a1);
        }
        *(float2*)&g_qw[((size_t)b * M_ + m0 + m) * G_ + g0] = make_float2(a0, a1);
    }
}

// ============================================================================
// k3: main attention. 2 centers/warp, 16 centers/block, 4 blocks/SM.
// W2 and x_v are consumed in fp16 to halve L1 wavefronts on the two
// dominant byte streams.
// ============================================================================
__global__ void __launch_bounds__(256, 4) k3_main(
    const float* __restrict__ cpos, const float* __restrict__ pos,
    const int*   __restrict__ idx,
    const float* __restrict__ pe_w1, const float* __restrict__ pe_s, const float* __restrict__ pe_b,
    const float* __restrict__ pe_w2, const float* __restrict__ pe_b2,
    const float* __restrict__ we_w2, const float* __restrict__ we_b2,
    float* __restrict__ out)
{
    __shared__ __align__(16) __half s_pew2h[64 * 68];        // [j][o] fp16, pad 68
    __shared__ __align__(16) float  s_stg[8 * 2 * 8 * 36];   // [w][c][g][36]
    __shared__ __align__(16) float  s_w[16 * 16 * 8];        // softmax weights
    __shared__ __align__(16) float4 s_npos[16 * 16];
    __shared__ __align__(16) float  s_out[16 * 68];
    __shared__ int   s_nidx[16 * 16];
    __shared__ float s_pes[64], s_peb[64], s_peb2[64];
    __shared__ float s_wew2[64];
    __shared__ float s_web2[8];

    int b = blockIdx.y;
    int m_base = blockIdx.x * 16;
    int t = threadIdx.x;
    int w = t >> 5, l = t & 31;

    // ---- cooperative constant loads ----
    for (int i = t; i < 64 * 64; i += 256) {
        int j = i >> 6, o = i & 63;
        s_pew2h[j * 68 + o] = __float2half_rn(pe_w2[i]);
    }
    for (int i = t; i < 64; i += 256) { s_pes[i] = pe_s[i]; s_peb[i] = pe_b[i]; s_peb2[i] = pe_b2[i]; }
    if (t < 64) s_wew2[t] = we_w2[t];
    if (t < 8)  s_web2[t] = we_b2[t];

    int half_ = l >> 4;           // 0/1: which center of the warp's pair
    int cc    = w * 2 + half_;
    int m     = m_base + cc;

    // ---- neighbor setup: lane (half_, k=l&15) ----
    {
        int k = l & 15;
        int n = idx[((size_t)b * M_ + m) * K_ + k];
        s_nidx[cc * 16 + k] = n;
        const float* pp = pos  + ((size_t)b * N_ + n) * 3;
        const float* cp = cpos + ((size_t)b * M_ + m) * 3;
        s_npos[cc * 16 + k] = make_float4(pp[0] - cp[0], pp[1] - cp[1], pp[2] - cp[2], 0.f);
    }
    __syncthreads();

    // ---- Phase A: logits + softmax, both centers in parallel across halves ----
    {
        int k = l & 15;
        int n = s_nidx[cc * 16 + k];
        const float4* qwp = (const float4*)&g_qw[((size_t)b * M_ + m) * G_];
        float4 qa = qwp[0], qb = qwp[1];
        const float4* kgp = (const float4*)&g_kgp[((size_t)b * N_ + n) * G_];
        float4 k0 = kgp[0], k1 = kgp[1];
        float h[8];
        h[0] = fmaxf(k0.x + qa.x, 0.f); h[1] = fmaxf(k0.y + qa.y, 0.f);
        h[2] = fmaxf(k0.z + qa.z, 0.f); h[3] = fmaxf(k0.w + qa.w, 0.f);
        h[4] = fmaxf(k1.x + qb.x, 0.f); h[5] = fmaxf(k1.y + qb.y, 0.f);
        h[6] = fmaxf(k1.z + qb.z, 0.f); h[7] = fmaxf(k1.w + qb.w, 0.f);

        float4 lgA = *(const float4*)&s_web2[0];
        float4 lgB = *(const float4*)&s_web2[4];
        #pragma unroll
        for (int j = 0; j < 8; j++) {
            float hj = h[j];
            float4 wA = *(const float4*)&s_wew2[j * 8];
            float4 wB = *(const float4*)&s_wew2[j * 8 + 4];
            lgA.x = fmaf(hj, wA.x, lgA.x); lgA.y = fmaf(hj, wA.y, lgA.y);
            lgA.z = fmaf(hj, wA.z, lgA.z); lgA.w = fmaf(hj, wA.w, lgA.w);
            lgB.x = fmaf(hj, wB.x, lgB.x); lgB.y = fmaf(hj, wB.y, lgB.y);
            lgB.z = fmaf(hj, wB.z, lgB.z); lgB.w = fmaf(hj, wB.w, lgB.w);
        }
        float lg[8] = {lgA.x, lgA.y, lgA.z, lgA.w, lgB.x, lgB.y, lgB.z, lgB.w};
        float mx[8];
        #pragma unroll
        for (int u = 0; u < 8; u++) mx[u] = lg[u];
        #pragma unroll
        for (int mask = 1; mask <= 8; mask <<= 1)
            #pragma unroll
            for (int u = 0; u < 8; u++)
                mx[u] = fmaxf(mx[u], __shfl_xor_sync(0xffffffffu, mx[u], mask));
        float e[8], sm[8];
        #pragma unroll
        for (int u = 0; u < 8; u++) { e[u] = __expf(lg[u] - mx[u]); sm[u] = e[u]; }
        #pragma unroll
        for (int mask = 1; mask <= 8; mask <<= 1)
            #pragma unroll
            for (int u = 0; u < 8; u++)
                sm[u] += __shfl_xor_sync(0xffffffffu, sm[u], mask);
        float* wp = &s_w[(cc * 16 + k) * 8];
        *(float4*)&wp[0] = make_float4(e[0] / sm[0], e[1] / sm[1], e[2] / sm[2], e[3] / sm[3]);
        *(float4*)&wp[4] = make_float4(e[4] / sm[4], e[5] / sm[5], e[6] / sm[6], e[7] / sm[7]);
    }
    __syncwarp();

    // ---- Phase B: S[c][g][j] in registers; lane owns j0=2l, j1=2l+1 ----
    float S0[2][8], S1[2][8];
    {
        int j0 = 2 * l, j1 = j0 + 1;
        float wx0 = pe_w1[j0], wy0 = pe_w1[64 + j0], wz0 = pe_w1[128 + j0];
        float wx1 = pe_w1[j1], wy1 = pe_w1[64 + j1], wz1 = pe_w1[128 + j1];
        float ps0 = s_pes[j0], pb0 = s_peb[j0];
        float ps1 = s_pes[j1], pb1 = s_peb[j1];

        #pragma unroll
        for (int c = 0; c < 2; c++) {
            int ccB = w * 2 + c;
            #pragma unroll
            for (int g = 0; g < 8; g++) { S0[c][g] = 0.f; S1[c][g] = 0.f; }
            #pragma unroll
            for (int kk = 0; kk < 16; kk++) {
                float4 np = s_npos[ccB * 16 + kk];
                float d0 = fmaf(np.z, wz0, fmaf(np.y, wy0, np.x * wx0));
                float d1 = fmaf(np.z, wz1, fmaf(np.y, wy1, np.x * wx1));
                float t0 = fmaxf(fmaf(d0, ps0, pb0), 0.f);
                float t1 = fmaxf(fmaf(d1, ps1, pb1), 0.f);
                const float* wp = &s_w[(ccB * 16 + kk) * 8];
                float4 wa = *(const float4*)&wp[0];
                float4 wb = *(const float4*)&wp[4];
                S0[c][0] = fmaf(t0, wa.x, S0[c][0]); S1[c][0] = fmaf(t1, wa.x, S1[c][0]);
                S0[c][1] = fmaf(t0, wa.y, S0[c][1]); S1[c][1] = fmaf(t1, wa.y, S1[c][1]);
                S0[c][2] = fmaf(t0, wa.z, S0[c][2]); S1[c][2] = fmaf(t1, wa.z, S1[c][2]);
                S0[c][3] = fmaf(t0, wa.w, S0[c][3]); S1[c][3] = fmaf(t1, wa.w, S1[c][3]);
                S0[c][4] = fmaf(t0, wb.x, S0[c][4]); S1[c][4] = fmaf(t1, wb.x, S1[c][4]);
                S0[c][5] = fmaf(t0, wb.y, S0[c][5]); S1[c][5] = fmaf(t1, wb.y, S1[c][5]);
                S0[c][6] = fmaf(t0, wb.z, S0[c][6]); S1[c][6] = fmaf(t1, wb.z, S1[c][6]);
                S0[c][7] = fmaf(t0, wb.w, S0[c][7]); S1[c][7] = fmaf(t1, wb.w, S1[c][7]);
            }
        }
    }

    // ---- Phase C: chunked over j (2 chunks of 32). lane: (half_, o0=(l&15)*4) ----
    {
        int lo = l & 15;
        int o0 = lo * 4;
        int g  = lo >> 1;
        float4 acc = *(const float4*)&s_peb2[o0];
        float* stg = &s_stg[((w * 2 + half_) * 8 + g) * 36];
        int myChunk = l >> 4;
        int jl = (l & 15) * 2;

        #pragma unroll
        for (int ch = 0; ch < 2; ch++) {
            if (myChunk == ch) {
                #pragma unroll
                for (int c = 0; c < 2; c++) {
                    float* dst = &s_stg[((w * 2 + c) * 8) * 36];
                    #pragma unroll
                    for (int gg = 0; gg < 8; gg++)
                        *(float2*)&dst[gg * 36 + jl] = make_float2(S0[c][gg], S1[c][gg]);
                }
            }
            __syncwarp();
            int jb = ch * 32;
            #pragma unroll
            for (int jq = 0; jq < 32; jq += 4) {
                float4 sv = *(const float4*)&stg[jq];
                const __half* wr = &s_pew2h[(jb + jq) * 68 + o0];
                float4 w20 = ld_h4(wr);
                float4 w21 = ld_h4(wr + 68);
                float4 w22 = ld_h4(wr + 136);
                float4 w23 = ld_h4(wr + 204);
                acc.x = fmaf(sv.x, w20.x, acc.x); acc.y = fmaf(sv.x, w20.y, acc.y);
                acc.z = fmaf(sv.x, w20.z, acc.z); acc.w = fmaf(sv.x, w20.w, acc.w);
                acc.x = fmaf(sv.y, w21.x, acc.x); acc.y = fmaf(sv.y, w21.y, acc.y);
                acc.z = fmaf(sv.y, w21.z, acc.z); acc.w = fmaf(sv.y, w21.w, acc.w);
                acc.x = fmaf(sv.z, w22.x, acc.x); acc.y = fmaf(sv.z, w22.y, acc.y);
                acc.z = fmaf(sv.z, w22.z, acc.z); acc.w = fmaf(sv.z, w22.w, acc.w);
                acc.x = fmaf(sv.w, w23.x, acc.x); acc.y = fmaf(sv.w, w23.y, acc.y);
                acc.z = fmaf(sv.w, w23.z, acc.z); acc.w = fmaf(sv.w, w23.w, acc.w);
            }
            __syncwarp();
        }

        // xv gather part (fp16 rows, 128B per point)
        const __half* xvb = &g_xvh[((size_t)b * N_) * O_];
        #pragma unroll
        for (int kk = 0; kk < 16; kk++) {
            int   n  = s_nidx[cc * 16 + kk];
            float wk = s_w[(cc * 16 + kk) * 8 + g];
            float4 xv = ld_h4(&xvb[(size_t)n * O_ + o0]);
            acc.x = fmaf(wk, xv.x, acc.x);
            acc.y = fmaf(wk, xv.y, acc.y);
            acc.z = fmaf(wk, xv.z, acc.z);
            acc.w = fmaf(wk, xv.w, acc.w);
        }
        *(float4*)&s_out[cc * 68 + o0] = acc;
    }
    __syncthreads();

    // ---- coalesced transposed store: out[b][o][m_base + 0..15] ----
    {
        int mm = t & 15;
        #pragma unroll
        for (int o = t >> 4; o < 64; o += 16)
            out[((size_t)b * O_ + o) * M_ + m_base + mm] = s_out[mm * 68 + o];
    }
}

// ============================================================================
extern "C" void kernel_launch(void* const* d_in, const int* in_sizes, int n_in,
                              void* d_out, int out_size)
{
    const float* center_pos = (const float*)d_in[0];
    const float* center_fea = (const float*)d_in[1];
    const float* pos        = (const float*)d_in[2];
    const float* fea        = (const float*)d_in[3];
    const int*   idx        = (const int*)  d_in[4];
    const float* Wq   = (const float*)d_in[5];
    const float* bq   = (const float*)d_in[6];
    const float* Wk   = (const float*)d_in[7];
    const float* bk   = (const float*)d_in[8];
    const float* Wv   = (const float*)d_in[9];
    const float* bv   = (const float*)d_in[10];
    const float* cpe_w1 = (const float*)d_in[11];
    const float* cpe_s  = (const float*)d_in[12];
    const float* cpe_b  = (const float*)d_in[13];
    const float* cpe_w2 = (const float*)d_in[14];
    const float* cpe_b2 = (const float*)d_in[15];
    const float* pe_w1  = (const float*)d_in[16];
    const float* pe_s   = (const float*)d_in[17];
    const float* pe_b   = (const float*)d_in[18];
    const float* pe_w2  = (const float*)d_in[19];
    const float* pe_b2  = (const float*)d_in[20];
    const float* we_w1  = (const float*)d_in[21];
    const float* we_s   = (const float*)d_in[22];
    const float* we_b   = (const float*)d_in[23];
    const float* we_w2  = (const float*)d_in[24];
    const float* we_b2  = (const float*)d_in[25];
    float* out = (float*)d_out;

    k0_fold<<<1, 64>>>(Wq, bq, Wk, bk, cpe_w2, cpe_b2, we_w1, we_s, we_b);

    dim3 g12(N_ / 64, B_, 2);
    k12<<<g12, 256>>>(fea, Wv, bv, center_fea, center_pos, cpe_w1, cpe_s, cpe_b);

    dim3 g3(M_ / 16, B_);
    k3_main<<<g3, 256>>>(center_pos, pos, idx,
                         pe_w1, pe_s, pe_b, pe_w2, pe_b2,
                         we_w2, we_b2, out);
}

// round 7
// speedup vs baseline: 1.2836x; 1.0008x over previous
#include <cuda_runtime.h>
#include <cuda_bf16.h>
#include <cuda_fp16.h>
#include <cstdint>

#define B_ 4
#define N_ 16384
#define M_ 16384
#define K_ 16
#define C_ 64
#define O_ 64
#define G_ 8

// ---------------- device scratch (no allocations allowed) -------------------
__device__ __align__(16) float  g_WkP[C_ * G_];
__device__ __align__(16) float  g_bkP[G_];
__device__ __align__(16) float  g_WqP[C_ * G_];
__device__ __align__(16) float  g_cw2P[O_ * G_];
__device__ __align__(16) float  g_qconst[G_];
__device__ __align__(16) __half g_xvh[(size_t)B_ * N_ * O_];  // x_v per point (fp16)
__device__ __align__(16) float  g_kgp[(size_t)B_ * N_ * G_];  // x_k @ we_w1' (+bias)
__device__ __align__(16) float  g_qw[(size_t)B_ * M_ * G_];   // (cpr-x_q)@we_w1' + we_b

// Load 4 consecutive halfs -> float4 (8-byte aligned)
__device__ __forceinline__ float4 ld_h4(const __half* p) {
    uint2 r = *(const uint2*)p;
    float2 f0 = __half22float2(*reinterpret_cast<__half2*>(&r.x));
    float2 f1 = __half22float2(*reinterpret_cast<__half2*>(&r.y));
    return make_float4(f0.x, f0.y, f1.x, f1.y);
}

// ============================================================================
// k0: fold we_w1*we_s through Wk, Wq, cpe_w2; fold biases.  1 block, 512 thr.
// ============================================================================
__global__ void __launch_bounds__(512) k0_fold(
    const float* __restrict__ Wq, const float* __restrict__ bq,
    const float* __restrict__ Wk, const float* __restrict__ bk,
    const float* __restrict__ cpe_w2, const float* __restrict__ cpe_b2,
    const float* __restrict__ we_w1, const float* __restrict__ we_s,
    const float* __restrict__ we_b)
{
    __shared__ float w1p[512];
    int t = threadIdx.x;                 // 0..511
    w1p[t] = we_w1[t] * we_s[t & 7];
    __syncthreads();

    int c = t >> 3, g = t & 7;
    float aK = 0.f, aQ = 0.f, aC = 0.f;
    const float* wkr = Wk + c * 64;
    const float* wqr = Wq + c * 64;
    const float* cwr = cpe_w2 + c * 64;
    #pragma unroll 8
    for (int o = 0; o < 64; o++) {
        float wp = w1p[o * 8 + g];
        aK = fmaf(wkr[o], wp, aK);
        aQ = fmaf(wqr[o], wp, aQ);
        aC = fmaf(cwr[o], wp, aC);
    }
    g_WkP[t]  = aK;
    g_WqP[t]  = aQ;
    g_cw2P[t] = aC;

    if (t < 8) {
        float bkp = 0.f, qc = we_b[t];
        #pragma unroll 8
        for (int o = 0; o < 64; o++) {
            float wp = w1p[o * 8 + t];
            bkp = fmaf(bk[o], wp, bkp);
            qc  = fmaf(cpe_b2[o] - bq[o], wp, qc);
        }
        g_bkP[t]    = bkp;
        g_qconst[t] = qc;
    }
}

// ============================================================================
// k12: fused point-side (z=0) and center-side (z=1) projections, using k0's
// pre-folded weights.  grid (256, B, 2), block 256.
// ============================================================================
__global__ void __launch_bounds__(256) k12(
    const float* __restrict__ fea, const float* __restrict__ Wv, const float* __restrict__ bv,
    const float* __restrict__ cfea, const float* __restrict__ cpos,
    const float* __restrict__ cpe_w1, const float* __restrict__ cpe_s, const float* __restrict__ cpe_b)
{
    __shared__ __align__(16) float smem[8784];
    int t = threadIdx.x;
    int b = blockIdx.y;

    if (blockIdx.z == 0) {
        // ---------------- x_v (fp16) and kgp per point ----------------
        float* sfea = smem;              // [64][64]
        float* sWv  = smem + 4096;       // [64][64]
        float* sWkP = smem + 8192;       // [64][8]
        float* sbkP = smem + 8704;       // [8]

        int n0 = blockIdx.x * 64;
        const float* fbase = fea + (size_t)b * C_ * N_ + n0;
        for (int i = t; i < 4096; i += 256) {
            int c = i >> 6, n = i & 63;
            sfea[c * 64 + n] = fbase[(size_t)c * N_ + n];
        }
        for (int i = t; i < 4096; i += 256) sWv[i] = Wv[i];
        for (int i = t; i < 512;  i += 256) sWkP[i] = g_WkP[i];
        if (t < 8) sbkP[t] = g_bkP[t];
        __syncthreads();

        int n = t & 63, q = t >> 6;
        int ob = q * 16;
        int g0 = 2 * q;
        float acc[16];
        #pragma unroll
        for (int u = 0; u < 16; u++) acc[u] = bv[ob + u];
        float ak0 = sbkP[g0], ak1 = sbkP[g0 + 1];

        #pragma unroll 4
        for (int c = 0; c < 64; c++) {
            float f = sfea[c * 64 + n];
            #pragma unroll
            for (int u = 0; u < 16; u++) acc[u] = fmaf(f, sWv[c * 64 + ob + u], acc[u]);
            ak0 = fmaf(f, sWkP[c * 8 + g0],     ak0);
            ak1 = fmaf(f, sWkP[c * 8 + g0 + 1], ak1);
        }

        __half* xvo = &g_xvh[((size_t)b * N_ + n0 + n) * O_ + ob];
        union { uint4 u; __half2 h[4]; } p0, p1;
        #pragma unroll
        for (int u = 0; u < 4; u++) p0.h[u] = __floats2half2_rn(acc[2 * u],     acc[2 * u + 1]);
        #pragma unroll
        for (int u = 0; u < 4; u++) p1.h[u] = __floats2half2_rn(acc[8 + 2 * u], acc[8 + 2 * u + 1]);
        *(uint4*)xvo       = p0.u;
        *(uint4*)(xvo + 8) = p1.u;
        *(float2*)&g_kgp[((size_t)b * N_ + n0 + n) * G_ + g0] = make_float2(ak0, ak1);
    } else {
        // ---------------- qw per center ----------------
        float* sfea  = smem;             // [64][64]
        float* sWqP  = smem + 4096;      // [64][8]
        float* scw2P = smem + 4608;      // [64][8]
        float* sw1   = smem + 5120;      // [3][64]
        float* ss    = smem + 5312;      // [64]
        float* sb    = smem + 5376;      // [64]
        float* sqc   = smem + 5440;      // [8]

        int m0 = blockIdx.x * 64;
        const float* fbase = cfea + (size_t)b * C_ * M_ + m0;
        for (int i = t; i < 4096; i += 256) {
            int c = i >> 6, m = i & 63;
            sfea[c * 64 + m] = fbase[(size_t)c * M_ + m];
        }
        for (int i = t; i < 512; i += 256) { sWqP[i] = g_WqP[i]; scw2P[i] = g_cw2P[i]; }
        if (t < 192) sw1[t] = cpe_w1[t];
        if (t < 64)  { ss[t] = cpe_s[t]; sb[t] = cpe_b[t]; }
        if (t < 8)   sqc[t] = g_qconst[t];
        __syncthreads();

        int m = t & 63, q = t >> 6, g0 = 2 * q;
        float a0 = sqc[g0], a1 = sqc[g0 + 1];

        #pragma unroll 4
        for (int c = 0; c < 64; c++) {
            float f = sfea[c * 64 + m];
            a0 = fmaf(-f, sWqP[c * 8 + g0],     a0);
            a1 = fmaf(-f, sWqP[c * 8 + g0 + 1], a1);
        }
        const float* cp = cpos + ((size_t)b * M_ + m0 + m) * 3;
        float x = cp[0], y = cp[1], z = cp[2];
        #pragma unroll 4
        for (int o = 0; o < 64; o++) {
            float d  = fmaf(z, sw1[128 + o], fmaf(y, sw1[64 + o], x * sw1[o]));
            float rc = fmaxf(fmaf(d, ss[o], sb[o]), 0.f);
            a0 = fmaf(rc, scw2P[o * 8 + g0],     a0);
            a1 = fmaf(rc, scw2P[o * 8 + g0 + 1], a1);
        }
        *(float2*)&g_qw[((size_t)b * M_ + m0 + m) * G_ + g0] = make_float2(a0, a1);
    }
}

// ============================================================================
// k3: main attention. 2 centers/warp, 16 centers/block, 4 blocks/SM.
// fp16 on all high-traffic smem paths: W2, softmax weights, S staging, x_v.
// ============================================================================
__global__ void __launch_bounds__(256, 4) k3_main(
    const float* __restrict__ cpos, const float* __restrict__ pos,
    const int*   __restrict__ idx,
    const float* __restrict__ pe_w1, const float* __restrict__ pe_s, const float* __restrict__ pe_b,
    const float* __restrict__ pe_w2, const float* __restrict__ pe_b2,
    const float* __restrict__ we_w2, const float* __restrict__ we_b2,
    float* __restrict__ out)
{
    __shared__ __align__(16) __half s_pew2h[64 * 68];        // [j][o] fp16, pad 68
    __shared__ __align__(16) __half s_stgh[8 * 2 * 8 * 36];  // [w][c][g][36] fp16
    __shared__ __align__(16) __half s_wh[16 * 16 * 8];       // softmax weights fp16
    __shared__ __align__(16) float4 s_npos[16 * 16];
    __shared__ __align__(16) float  s_out[16 * 68];
    __shared__ int   s_nidx[16 * 16];
    __shared__ float s_pes[64], s_peb[64], s_peb2[64];
    __shared__ float s_wew2[64];
    __shared__ float s_web2[8];

    int b = blockIdx.y;
    int m_base = blockIdx.x * 16;
    int t = threadIdx.x;
    int w = t >> 5, l = t & 31;

    // ---- cooperative constant loads ----
    for (int i = t; i < 64 * 64; i += 256) {
        int j = i >> 6, o = i & 63;
        s_pew2h[j * 68 + o] = __float2half_rn(pe_w2[i]);
    }
    for (int i = t; i < 64; i += 256) { s_pes[i] = pe_s[i]; s_peb[i] = pe_b[i]; s_peb2[i] = pe_b2[i]; }
    if (t < 64) s_wew2[t] = we_w2[t];
    if (t < 8)  s_web2[t] = we_b2[t];

    int half_ = l >> 4;           // 0/1: which center of the warp's pair
    int cc    = w * 2 + half_;
    int m     = m_base + cc;

    // ---- neighbor setup: lane (half_, k=l&15) ----
    {
        int k = l & 15;
        int n = idx[((size_t)b * M_ + m) * K_ + k];
        s_nidx[cc * 16 + k] = n;
        const float* pp = pos  + ((size_t)b * N_ + n) * 3;
        const float* cp = cpos + ((size_t)b * M_ + m) * 3;
        s_npos[cc * 16 + k] = make_float4(pp[0] - cp[0], pp[1] - cp[1], pp[2] - cp[2], 0.f);
    }
    __syncthreads();

    // ---- Phase A: logits + softmax, both centers in parallel across halves ----
    {
        int k = l & 15;
        int n = s_nidx[cc * 16 + k];
        const float4* qwp = (const float4*)&g_qw[((size_t)b * M_ + m) * G_];
        float4 qa = qwp[0], qb = qwp[1];
        const float4* kgp = (const float4*)&g_kgp[((size_t)b * N_ + n) * G_];
        float4 k0 = kgp[0], k1 = kgp[1];
        float h[8];
        h[0] = fmaxf(k0.x + qa.x, 0.f); h[1] = fmaxf(k0.y + qa.y, 0.f);
        h[2] = fmaxf(k0.z + qa.z, 0.f); h[3] = fmaxf(k0.w + qa.w, 0.f);
        h[4] = fmaxf(k1.x + qb.x, 0.f); h[5] = fmaxf(k1.y + qb.y, 0.f);
        h[6] = fmaxf(k1.z + qb.z, 0.f); h[7] = fmaxf(k1.w + qb.w, 0.f);

        float4 lgA = *(const float4*)&s_web2[0];
        float4 lgB = *(const float4*)&s_web2[4];
        #pragma unroll
        for (int j = 0; j < 8; j++) {
            float hj = h[j];
            float4 wA = *(const float4*)&s_wew2[j * 8];
            float4 wB = *(const float4*)&s_wew2[j * 8 + 4];
            lgA.x = fmaf(hj, wA.x, lgA.x); lgA.y = fmaf(hj, wA.y, lgA.y);
            lgA.z = fmaf(hj, wA.z, lgA.z); lgA.w = fmaf(hj, wA.w, lgA.w);
            lgB.x = fmaf(hj, wB.x, lgB.x); lgB.y = fmaf(hj, wB.y, lgB.y);
            lgB.z = fmaf(hj, wB.z, lgB.z); lgB.w = fmaf(hj, wB.w, lgB.w);
        }
        float lg[8] = {lgA.x, lgA.y, lgA.z, lgA.w, lgB.x, lgB.y, lgB.z, lgB.w};
        float mx[8];
        #pragma unroll
        for (int u = 0; u < 8; u++) mx[u] = lg[u];
        #pragma unroll
        for (int mask = 1; mask <= 8; mask <<= 1)
            #pragma unroll
            for (int u = 0; u < 8; u++)
                mx[u] = fmaxf(mx[u], __shfl_xor_sync(0xffffffffu, mx[u], mask));
        float e[8], sm[8];
        #pragma unroll
        for (int u = 0; u < 8; u++) { e[u] = __expf(lg[u] - mx[u]); sm[u] = e[u]; }
        #pragma unroll
        for (int mask = 1; mask <= 8; mask <<= 1)
            #pragma unroll
            for (int u = 0; u < 8; u++)
                sm[u] += __shfl_xor_sync(0xffffffffu, sm[u], mask);
        union { uint4 u; __half2 h2[4]; } pw;
        #pragma unroll
        for (int u = 0; u < 4; u++)
            pw.h2[u] = __floats2half2_rn(e[2 * u] / sm[2 * u], e[2 * u + 1] / sm[2 * u + 1]);
        *(uint4*)&s_wh[(cc * 16 + k) * 8] = pw.u;
    }
    __syncwarp();

    // ---- Phase B: S[c][g][j] in registers; lane owns j0=2l, j1=2l+1 ----
    float S0[2][8], S1[2][8];
    {
        int j0 = 2 * l, j1 = j0 + 1;
        float wx0 = pe_w1[j0], wy0 = pe_w1[64 + j0], wz0 = pe_w1[128 + j0];
        float wx1 = pe_w1[j1], wy1 = pe_w1[64 + j1], wz1 = pe_w1[128 + j1];
        float ps0 = s_pes[j0], pb0 = s_peb[j0];
        float ps1 = s_pes[j1], pb1 = s_peb[j1];

        #pragma unroll
        for (int c = 0; c < 2; c++) {
            int ccB = w * 2 + c;
            #pragma unroll
            for (int g = 0; g < 8; g++) { S0[c][g] = 0.f; S1[c][g] = 0.f; }
            #pragma unroll
            for (int kk = 0; kk < 16; kk++) {
                float4 np = s_npos[ccB * 16 + kk];
                float d0 = fmaf(np.z, wz0, fmaf(np.y, wy0, np.x * wx0));
                float d1 = fmaf(np.z, wz1, fmaf(np.y, wy1, np.x * wx1));
                float t0 = fmaxf(fmaf(d0, ps0, pb0), 0.f);
                float t1 = fmaxf(fmaf(d1, ps1, pb1), 0.f);
                uint4 rw = *(const uint4*)&s_wh[(ccB * 16 + kk) * 8];
                float2 f0 = __half22float2(*reinterpret_cast<__half2*>(&rw.x));
                float2 f1 = __half22float2(*reinterpret_cast<__half2*>(&rw.y));
                float2 f2 = __half22float2(*reinterpret_cast<__half2*>(&rw.z));
                float2 f3 = __half22float2(*reinterpret_cast<__half2*>(&rw.w));
                S0[c][0] = fmaf(t0, f0.x, S0[c][0]); S1[c][0] = fmaf(t1, f0.x, S1[c][0]);
                S0[c][1] = fmaf(t0, f0.y, S0[c][1]); S1[c][1] = fmaf(t1, f0.y, S1[c][1]);
                S0[c][2] = fmaf(t0, f1.x, S0[c][2]); S1[c][2] = fmaf(t1, f1.x, S1[c][2]);
                S0[c][3] = fmaf(t0, f1.y, S0[c][3]); S1[c][3] = fmaf(t1, f1.y, S1[c][3]);
                S0[c][4] = fmaf(t0, f2.x, S0[c][4]); S1[c][4] = fmaf(t1, f2.x, S1[c][4]);
                S0[c][5] = fmaf(t0, f2.y, S0[c][5]); S1[c][5] = fmaf(t1, f2.y, S1[c][5]);
                S0[c][6] = fmaf(t0, f3.x, S0[c][6]); S1[c][6] = fmaf(t1, f3.x, S1[c][6]);
                S0[c][7] = fmaf(t0, f3.y, S0[c][7]); S1[c][7] = fmaf(t1, f3.y, S1[c][7]);
            }
        }
    }

    // ---- Phase C: chunked over j (2 chunks of 32). lane: (half_, o0=(l&15)*4) ----
    {
        int lo = l & 15;
        int o0 = lo * 4;
        int g  = lo >> 1;
        float4 acc = *(const float4*)&s_peb2[o0];
        __half* warpStg = &s_stgh[w * (2 * 8 * 36)];
        const __half* stg = &warpStg[(half_ * 8 + g) * 36];
        int myChunk = l >> 4;
        int jl = (l & 15) * 2;   // local j (in halfs) within chunk

        #pragma unroll
        for (int ch = 0; ch < 2; ch++) {
            if (myChunk == ch) {
                #pragma unroll
                for (int c = 0; c < 2; c++) {
                    __half* dst = &warpStg[(c * 8) * 36];
                    #pragma unroll
                    for (int gg = 0; gg < 8; gg++)
                        *(__half2*)&dst[gg * 36 + jl] = __floats2half2_rn(S0[c][gg], S1[c][gg]);
                }
            }
            __syncwarp();
            int jb = ch * 32;
            #pragma unroll
            for (int jq = 0; jq < 32; jq += 4) {
                uint2 rs = *(const uint2*)&stg[jq];
                float2 sa = __half22float2(*reinterpret_cast<__half2*>(&rs.x));
                float2 sb = __half22float2(*reinterpret_cast<__half2*>(&rs.y));
                const __half* wr = &s_pew2h[(jb + jq) * 68 + o0];
                float4 w20 = ld_h4(wr);
                float4 w21 = ld_h4(wr + 68);
                float4 w22 = ld_h4(wr + 136);
                float4 w23 = ld_h4(wr + 204);
                acc.x = fmaf(sa.x, w20.x, acc.x); acc.y = fmaf(sa.x, w20.y, acc.y);
                acc.z = fmaf(sa.x, w20.z, acc.z); acc.w = fmaf(sa.x, w20.w, acc.w);
                acc.x = fmaf(sa.y, w21.x, acc.x); acc.y = fmaf(sa.y, w21.y, acc.y);
                acc.z = fmaf(sa.y, w21.z, acc.z); acc.w = fmaf(sa.y, w21.w, acc.w);
                acc.x = fmaf(sb.x, w22.x, acc.x); acc.y = fmaf(sb.x, w22.y, acc.y);
                acc.z = fmaf(sb.x, w22.z, acc.z); acc.w = fmaf(sb.x, w22.w, acc.w);
                acc.x = fmaf(sb.y, w23.x, acc.x); acc.y = fmaf(sb.y, w23.y, acc.y);
                acc.z = fmaf(sb.y, w23.z, acc.z); acc.w = fmaf(sb.y, w23.w, acc.w);
            }
            __syncwarp();
        }

        // xv gather part (fp16 rows, 128B per point)
        const __half* xvb = &g_xvh[((size_t)b * N_) * O_];
        #pragma unroll
        for (int kk = 0; kk < 16; kk++) {
            int   n  = s_nidx[cc * 16 + kk];
            float wk = __half2float(s_wh[(cc * 16 + kk) * 8 + g]);
            float4 xv = ld_h4(&xvb[(size_t)n * O_ + o0]);
            acc.x = fmaf(wk, xv.x, acc.x);
            acc.y = fmaf(wk, xv.y, acc.y);
            acc.z = fmaf(wk, xv.z, acc.z);
            acc.w = fmaf(wk, xv.w, acc.w);
        }
        *(float4*)&s_out[cc * 68 + o0] = acc;
    }
    __syncthreads();

    // ---- coalesced transposed store: out[b][o][m_base + 0..15] ----
    {
        int mm = t & 15;
        #pragma unroll
        for (int o = t >> 4; o < 64; o += 16)
            out[((size_t)b * O_ + o) * M_ + m_base + mm] = s_out[mm * 68 + o];
    }
}

// ============================================================================
extern "C" void kernel_launch(void* const* d_in, const int* in_sizes, int n_in,
                              void* d_out, int out_size)
{
    const float* center_pos = (const float*)d_in[0];
    const float* center_fea = (const float*)d_in[1];
    const float* pos        = (const float*)d_in[2];
    const float* fea        = (const float*)d_in[3];
    const int*   idx        = (const int*)  d_in[4];
    const float* Wq   = (const float*)d_in[5];
    const float* bq   = (const float*)d_in[6];
    const float* Wk   = (const float*)d_in[7];
    const float* bk   = (const float*)d_in[8];
    const float* Wv   = (const float*)d_in[9];
    const float* bv   = (const float*)d_in[10];
    const float* cpe_w1 = (const float*)d_in[11];
    const float* cpe_s  = (const float*)d_in[12];
    const float* cpe_b  = (const float*)d_in[13];
    const float* cpe_w2 = (const float*)d_in[14];
    const float* cpe_b2 = (const float*)d_in[15];
    const float* pe_w1  = (const float*)d_in[16];
    const float* pe_s   = (const float*)d_in[17];
    const float* pe_b   = (const float*)d_in[18];
    const float* pe_w2  = (const float*)d_in[19];
    const float* pe_b2  = (const float*)d_in[20];
    const float* we_w1  = (const float*)d_in[21];
    const float* we_s   = (const float*)d_in[22];
    const float* we_b   = (const float*)d_in[23];
    const float* we_w2  = (const float*)d_in[24];
    const float* we_b2  = (const float*)d_in[25];
    float* out = (float*)d_out;

    k0_fold<<<1, 512>>>(Wq, bq, Wk, bk, cpe_w2, cpe_b2, we_w1, we_s, we_b);

    dim3 g12(N_ / 64, B_, 2);
    k12<<<g12, 256>>>(fea, Wv, bv, center_fea, center_pos, cpe_w1, cpe_s, cpe_b);

    dim3 g3(M_ / 16, B_);
    k3_main<<<g3, 256>>>(center_pos, pos, idx,
                         pe_w1, pe_s, pe_b, pe_w2, pe_b2,
                         we_w2, we_b2, out);
}